// round 2
// baseline (speedup 1.0000x reference)
#include <cuda_runtime.h>

// Problem constants (match reference setup_inputs)
#define BQ 8
#define CC 64
#define HH 512
#define WW 512
#define OO 64
#define SS 4
// hs = ws = 128; block elements per pooled tile = 128*128 = 16384

// Scratch (allocation-free rule: __device__ globals)
__device__ float g_pooled[BQ * CC * SS * SS];    // [b, c, i, j]
__device__ float g_weighted[BQ * OO * SS * SS];  // [b, o, i, j]

// ---------------------------------------------------------------------------
// Kernel 1: segment mean-pool.
// Grid: BQ*CC*SS CTAs; each CTA handles one (b, c, i) stripe = 128 rows x 512 cols.
// 256 threads, float4 loads. Thread's column index (idx & 127) is invariant
// under the +=256 stride, so each warp sees exactly one j segment.
// ---------------------------------------------------------------------------
__global__ __launch_bounds__(256) void pool_kernel(const float* __restrict__ x) {
    int bi = blockIdx.x;             // b*CC*SS + c*SS + i
    int i  = bi % SS;
    int c  = (bi / SS) % CC;
    int b  = bi / (SS * CC);

    const float4* base = reinterpret_cast<const float4*>(
        x + (((size_t)(b * CC + c)) * HH + (size_t)i * 128) * WW);

    int tid = threadIdx.x;
    float sum = 0.0f;
    // 128 rows * 128 float4/row = 16384 float4 per stripe
    #pragma unroll 8
    for (int idx = tid; idx < 128 * 128; idx += 256) {
        float4 v = base[idx];        // row*128 + col4 == idx
        sum += (v.x + v.y) + (v.z + v.w);
    }

    // warp reduce (all lanes in a warp share the same j)
    #pragma unroll
    for (int off = 16; off; off >>= 1)
        sum += __shfl_down_sync(0xffffffffu, sum, off);

    __shared__ float sj[SS];
    if (tid < SS) sj[tid] = 0.0f;
    __syncthreads();

    int wid = tid >> 5;
    int j   = wid & 3;               // warps 0-3 -> j 0-3, warps 4-7 -> j 0-3
    if ((tid & 31) == 0) atomicAdd(&sj[j], sum);
    __syncthreads();

    if (tid < SS)
        g_pooled[((size_t)(b * CC + c) * SS + i) * SS + tid] =
            sj[tid] * (1.0f / 16384.0f);
}

// ---------------------------------------------------------------------------
// Kernel 2: per-tile linear + bias + seg_w. Negligible cost.
// Grid: BQ*SS*SS CTAs of OO threads; CTA handles one (b, i, j) tile.
// ---------------------------------------------------------------------------
__global__ __launch_bounds__(OO) void mix_kernel(const float* __restrict__ Wm,
                                                 const float* __restrict__ bias,
                                                 const float* __restrict__ seg_w) {
    int blk = blockIdx.x;            // b*16 + i*4 + j
    int ij  = blk & 15;
    int b   = blk >> 4;

    __shared__ float pool[CC];
    int o = threadIdx.x;
    pool[o] = g_pooled[(size_t)(b * CC + o) * (SS * SS) + ij];
    __syncthreads();

    float acc = 0.0f;
    const float* wrow = Wm + (size_t)o * CC;
    #pragma unroll
    for (int c = 0; c < CC; c++) acc += pool[c] * wrow[c];

    acc = (acc + bias[o]) * seg_w[ij];
    g_weighted[(size_t)(b * OO + o) * (SS * SS) + ij] = acc;
}

// ---------------------------------------------------------------------------
// Kernel 3: broadcast weighted tile values over 128x128 blocks.
// Each CTA writes 2048 float4 = 8192 floats = 16 consecutive rows of one
// (b,o) plane -> plane p and row-segment i are constant per CTA; each
// thread's column (tid & 127) is constant -> j constant per thread.
// One __ldg per thread, 8 contiguous float4 stores.
// ---------------------------------------------------------------------------
__global__ __launch_bounds__(256) void bcast_kernel(float4* __restrict__ out) {
    size_t gbase = (size_t)blockIdx.x * 2048;     // f4 index of CTA start
    size_t r0    = gbase >> 7;                    // starting row (global)
    int    h0    = (int)(r0 & (HH - 1));          // row within plane
    size_t p     = r0 >> 9;                       // plane = b*OO + o
    int    i     = h0 >> 7;                       // row segment (const: 16 rows, h0 % 16 == 0)

    int tid = threadIdx.x;
    int j   = (tid & 127) >> 5;                   // column segment (const per thread)
    float v = __ldg(&g_weighted[p * (SS * SS) + i * SS + j]);
    float4 v4 = make_float4(v, v, v, v);

    float4* dst = out + gbase + tid;
    #pragma unroll
    for (int k = 0; k < 8; k++)
        dst[(size_t)k * 256] = v4;
}

// ---------------------------------------------------------------------------
extern "C" void kernel_launch(void* const* d_in, const int* in_sizes, int n_in,
                              void* d_out, int out_size) {
    const float* x     = (const float*)d_in[0];   // [B, C, H, W]
    const float* Wm    = (const float*)d_in[1];   // [O, C]
    const float* bias  = (const float*)d_in[2];   // [O]
    const float* seg_w = (const float*)d_in[3];   // [S, S]
    float* out = (float*)d_out;                   // [B, O, H, W]

    pool_kernel<<<BQ * CC * SS, 256>>>(x);
    mix_kernel<<<BQ * SS * SS, OO>>>(Wm, bias, seg_w);

    // total float4 in output = 8*64*512*512/4 = 33554432; 2048 f4 per CTA
    int bcast_blocks = (BQ * OO * HH * WW / 4) / 2048;  // 16384
    bcast_kernel<<<bcast_blocks, 256>>>((float4*)out);
}